// round 1
// baseline (speedup 1.0000x reference)
#include <cuda_runtime.h>
#include <math.h>

#define BB 4
#define CC 128
#define HH 128
#define WW 240
#define EE 64
#define RNG 4
#define KK 9          // 2*RNG+1
#define HW (HH*WW)    // 30720

// Scratch: normalized embeddings, layout [tensor][b][h][w][e] with e contiguous.
// 2 * 4*128*240*64 floats = 62.9 MB.
__device__ float g_emb[2][(size_t)BB * HW * EE];

// ---------------------------------------------------------------------------
// Embed: y[e] = sum_c phi[e][c] * F[b][c][h][w]; normalize over e; store [bhwe].
// One thread per pixel, 64 accumulators, phi staged in smem as float4 chunks.
// ---------------------------------------------------------------------------
__global__ __launch_bounds__(256, 2)
void embed_kernel(const float* __restrict__ FL,
                  const float* __restrict__ FR,
                  const float* __restrict__ phi)
{
    __shared__ float4 phi_s[EE * (CC / 4)];   // [e*32 + c4], 32 KB

    const int t = threadIdx.x;
    for (int i = t; i < EE * (CC / 4); i += blockDim.x)
        phi_s[i] = reinterpret_cast<const float4*>(phi)[i];
    __syncthreads();

    const int q      = blockIdx.x * blockDim.x + t;   // pixel within image (h*W+w)
    const int b      = blockIdx.y;
    const int tensor = blockIdx.z;
    if (q >= HW) return;

    const float* __restrict__ F =
        (tensor == 0 ? FL : FR) + (size_t)b * CC * HW + q;

    float acc[EE];
#pragma unroll
    for (int e = 0; e < EE; e++) acc[e] = 0.0f;

    for (int c4 = 0; c4 < CC / 4; c4++) {
        const float f0 = F[(size_t)(c4 * 4 + 0) * HW];
        const float f1 = F[(size_t)(c4 * 4 + 1) * HW];
        const float f2 = F[(size_t)(c4 * 4 + 2) * HW];
        const float f3 = F[(size_t)(c4 * 4 + 3) * HW];
#pragma unroll
        for (int e = 0; e < EE; e++) {
            const float4 p = phi_s[e * (CC / 4) + c4];
            float a = acc[e];
            a = fmaf(p.x, f0, a);
            a = fmaf(p.y, f1, a);
            a = fmaf(p.z, f2, a);
            a = fmaf(p.w, f3, a);
            acc[e] = a;
        }
    }

    float s = 0.0f;
#pragma unroll
    for (int e = 0; e < EE; e++) s = fmaf(acc[e], acc[e], s);
    const float inv = 1.0f / (sqrtf(s) + 1e-6f);

    float4* __restrict__ outp =
        reinterpret_cast<float4*>(&g_emb[tensor][((size_t)b * HW + q) * EE]);
#pragma unroll
    for (int e4 = 0; e4 < EE / 4; e4++) {
        float4 v;
        v.x = acc[e4 * 4 + 0] * inv;
        v.y = acc[e4 * 4 + 1] * inv;
        v.z = acc[e4 * 4 + 2] * inv;
        v.w = acc[e4 * 4 + 3] * inv;
        outp[e4] = v;
    }
}

// ---------------------------------------------------------------------------
// Correlation: for each pixel, 9 taps of lerp-gathered FR dotted with FL.
// ---------------------------------------------------------------------------
__global__ __launch_bounds__(256, 2)
void corr_kernel(const float* __restrict__ d0,
                 float* __restrict__ out)
{
    const int q = blockIdx.x * blockDim.x + threadIdx.x;
    if (q >= HW) return;
    const int b = blockIdx.y;
    const int h = q / WW;
    const int w = q - h * WW;

    // Load FL vector (64 floats) into registers.
    const float4* __restrict__ flp =
        reinterpret_cast<const float4*>(&g_emb[0][((size_t)b * HW + q) * EE]);
    float fl[EE];
#pragma unroll
    for (int e4 = 0; e4 < EE / 4; e4++) {
        const float4 v = flp[e4];
        fl[e4 * 4 + 0] = v.x;
        fl[e4 * 4 + 1] = v.y;
        fl[e4 * 4 + 2] = v.z;
        fl[e4 * 4 + 3] = v.w;
    }

    const float d = d0[(size_t)b * HW + q];
    const float* __restrict__ fr_row =
        &g_emb[1][((size_t)b * HW + (size_t)h * WW) * EE];

#pragma unroll
    for (int k = 0; k < KK; k++) {
        const float delta = (float)(k - RNG);
        const float xp = (float)w - d - delta;
        const float x0 = floorf(xp);
        const float frac = xp - x0;
        int i0 = (int)x0;
        int i1 = i0 + 1;
        i0 = min(max(i0, 0), WW - 1);
        i1 = min(max(i1, 0), WW - 1);

        const float4* __restrict__ g0 =
            reinterpret_cast<const float4*>(&fr_row[(size_t)i0 * EE]);
        const float4* __restrict__ g1 =
            reinterpret_cast<const float4*>(&fr_row[(size_t)i1 * EE]);

        float dot = 0.0f;
#pragma unroll
        for (int e4 = 0; e4 < EE / 4; e4++) {
            const float4 a = g0[e4];
            const float4 c = g1[e4];
            float v;
            v = fmaf(frac, c.x - a.x, a.x); dot = fmaf(fl[e4 * 4 + 0], v, dot);
            v = fmaf(frac, c.y - a.y, a.y); dot = fmaf(fl[e4 * 4 + 1], v, dot);
            v = fmaf(frac, c.z - a.z, a.z); dot = fmaf(fl[e4 * 4 + 2], v, dot);
            v = fmaf(frac, c.w - a.w, a.w); dot = fmaf(fl[e4 * 4 + 3], v, dot);
        }
        out[(((size_t)b * KK + k) * HH + h) * WW + w] = dot;
    }
}

extern "C" void kernel_launch(void* const* d_in, const int* in_sizes, int n_in,
                              void* d_out, int out_size)
{
    const float* F_L   = (const float*)d_in[0];
    const float* F_R   = (const float*)d_in[1];
    const float* d0    = (const float*)d_in[2];
    const float* phi_w = (const float*)d_in[3];
    float* out = (float*)d_out;

    {
        dim3 grid((HW + 255) / 256, BB, 2);
        embed_kernel<<<grid, 256>>>(F_L, F_R, phi_w);
    }
    {
        dim3 grid((HW + 255) / 256, BB, 1);
        corr_kernel<<<grid, 256>>>(d0, out);
    }
}